// round 1
// baseline (speedup 1.0000x reference)
#include <cuda_runtime.h>

// ---------------- problem dims ----------------
constexpr int B_   = 8;
constexpr int IMG_ = 224;
constexpr int P_   = 16;
constexpr int G_   = 14;
constexpr int N_   = 196;   // G*G
constexpr int PD_  = 256;   // P*P
constexpr int D_   = 128;
constexpr int DFF_ = 256;
constexpr int C_   = 1000;
constexpr int M_   = B_ * N_;   // 1568 total token rows

constexpr float NEGBIG = -1e30f;

// ---------------- scratch (no alloc allowed -> device globals) ----------------
__device__ float g_patches[B_ * N_ * PD_];
__device__ float g_h[B_ * N_ * D_];
__device__ float g_q[B_ * N_ * D_];
__device__ float g_k[B_ * N_ * D_];
__device__ float g_v[B_ * N_ * D_];
__device__ float g_S[B_ * N_ * N_];
__device__ float g_ff[B_ * N_ * DFF_];
__device__ float g_m[B_ * N_];
__device__ float g_pool[B_ * D_];

// ---------------- patchify ----------------
__global__ void patchify_kernel(const float* __restrict__ x) {
    int idx = blockIdx.x * 256 + threadIdx.x;
    if (idx >= B_ * N_ * PD_) return;
    int j = idx % PD_;
    int n = (idx / PD_) % N_;
    int b = idx / (PD_ * N_);
    int gi = n / G_, gj = n % G_;
    int pi = j / P_, pj = j % P_;
    g_patches[idx] = x[((long)b * IMG_ + gi * P_ + pi) * IMG_ + gj * P_ + pj];
}

// ---------------- row max (for pnorm folding) ----------------
__global__ void rowmax_kernel(const float* __restrict__ X, float* __restrict__ m,
                              int rows, int cols) {
    int w = (blockIdx.x * blockDim.x + threadIdx.x) >> 5;
    int lane = threadIdx.x & 31;
    if (w >= rows) return;
    float v = NEGBIG;
    for (int c = lane; c < cols; c += 32) v = fmaxf(v, X[(long)w * cols + c]);
    #pragma unroll
    for (int off = 16; off; off >>= 1) v = fmaxf(v, __shfl_xor_sync(0xffffffffu, v, off));
    if (lane == 0) m[w] = v;
}

// ---------------- score row normalize (subtract row max over j) ----------------
__global__ void snorm_kernel(float* __restrict__ S, int rows, int cols) {
    int w = (blockIdx.x * blockDim.x + threadIdx.x) >> 5;
    int lane = threadIdx.x & 31;
    if (w >= rows) return;
    float vals[7];
    float mx = NEGBIG;
    int cnt = 0;
    for (int c = lane; c < cols; c += 32) {
        vals[cnt] = S[(long)w * cols + c];
        mx = fmaxf(mx, vals[cnt]);
        cnt++;
    }
    #pragma unroll
    for (int off = 16; off; off >>= 1) mx = fmaxf(mx, __shfl_xor_sync(0xffffffffu, mx, off));
    cnt = 0;
    for (int c = lane; c < cols; c += 32) {
        S[(long)w * cols + c] = vals[cnt] - mx;
        cnt++;
    }
}

// ---------------- tropical GEMM template ----------------
// out[r, n] = max_k ( A[r, k] + W[n*wN + k*wK] )    (+ epilogue)
enum {
    EPI_STORE = 0,        // plain
    EPI_POS = 1,          // + aux[(r % 196)*ldo + n]     (embed pos add)
    EPI_SUBROW = 2,       // - aux[r]                     (input pnorm folded)
    EPI_SUBROW_TAU = 3,   // max(acc - aux[r], tau[0])    (ff1 + tropical relu)
    EPI_PNORM_RESID = 4   // out = max(out_old, acc - rowmax(acc_row))  (needs BN >= Nout)
};

template <int BM, int BN, int BK, int TM, int TN, int EPI>
__global__ void __launch_bounds__((BM / TM) * (BN / TN))
trop_gemm(const float* __restrict__ A, int lda, long sA,
          const float* __restrict__ W, int wN, int wK, long sW,
          float* __restrict__ O, int ldo, long sO,
          int M, int Nout, int K,
          const float* __restrict__ aux,
          const float* __restrict__ tau) {
    constexpr int THREADS = (BM / TM) * (BN / TN);
    constexpr int APT = BM * BK / THREADS;
    constexpr int BPT = BN * BK / THREADS;

    __shared__ float As[BK][BM + 4];
    __shared__ float Bs[BK][BN + 4];

    int z = blockIdx.z;
    A += (long)z * sA;
    W += (long)z * sW;
    O += (long)z * sO;

    const int row0 = blockIdx.x * BM;
    const int n0 = blockIdx.y * BN;
    const int tid = threadIdx.x;
    const bool kcontig = (wK == 1);

    float apf[APT], bpf[BPT];
    const int nchunks = (K + BK - 1) / BK;

    auto loadA = [&](int c) {
        #pragma unroll
        for (int i = 0; i < APT; i++) {
            int e = tid + i * THREADS;
            int kk = e % BK, mm = e / BK;
            int k = c * BK + kk, r = row0 + mm;
            apf[i] = (r < M && k < K) ? A[(long)r * lda + k] : NEGBIG;
        }
    };
    auto loadB = [&](int c) {
        if (kcontig) {
            #pragma unroll
            for (int i = 0; i < BPT; i++) {
                int e = tid + i * THREADS;
                int kk = e % BK, n = e / BK;
                int k = c * BK + kk, nn = n0 + n;
                bpf[i] = (nn < Nout && k < K) ? W[(long)nn * wN + k] : NEGBIG;
            }
        } else {
            #pragma unroll
            for (int i = 0; i < BPT; i++) {
                int e = tid + i * THREADS;
                int n = e % BN, kk = e / BN;
                int k = c * BK + kk, nn = n0 + n;
                bpf[i] = (nn < Nout && k < K) ? W[(long)k * wK + nn] : NEGBIG;
            }
        }
    };
    auto storeAB = [&]() {
        #pragma unroll
        for (int i = 0; i < APT; i++) {
            int e = tid + i * THREADS;
            As[e % BK][e / BK] = apf[i];
        }
        if (kcontig) {
            #pragma unroll
            for (int i = 0; i < BPT; i++) {
                int e = tid + i * THREADS;
                Bs[e % BK][e / BK] = bpf[i];
            }
        } else {
            #pragma unroll
            for (int i = 0; i < BPT; i++) {
                int e = tid + i * THREADS;
                Bs[e / BN][e % BN] = bpf[i];
            }
        }
    };

    float acc[TM][TN];
    #pragma unroll
    for (int i = 0; i < TM; i++)
        #pragma unroll
        for (int j = 0; j < TN; j++) acc[i][j] = NEGBIG;

    const int tn = tid & 31;   // BN/TN == 32 always
    const int tm = tid >> 5;

    loadA(0);
    loadB(0);
    storeAB();
    __syncthreads();

    for (int c = 0; c < nchunks; c++) {
        bool more = (c + 1 < nchunks);
        if (more) {
            loadA(c + 1);
            loadB(c + 1);
        }
        #pragma unroll
        for (int kk = 0; kk < BK; kk++) {
            float a[TM], b[TN];
            #pragma unroll
            for (int i = 0; i < TM; i++) a[i] = As[kk][tm * TM + i];
            #pragma unroll
            for (int j = 0; j < TN; j++) b[j] = Bs[kk][tn * TN + j];
            #pragma unroll
            for (int i = 0; i < TM; i++)
                #pragma unroll
                for (int j = 0; j < TN; j++)
                    acc[i][j] = fmaxf(acc[i][j], a[i] + b[j]);
        }
        __syncthreads();
        if (more) {
            storeAB();
            __syncthreads();
        }
    }

    // ---- epilogue ----
    float rmax[TM];
    if (EPI == EPI_PNORM_RESID) {
        #pragma unroll
        for (int i = 0; i < TM; i++) {
            float r = acc[i][0];
            #pragma unroll
            for (int j = 1; j < TN; j++) r = fmaxf(r, acc[i][j]);
            #pragma unroll
            for (int off = 16; off; off >>= 1)
                r = fmaxf(r, __shfl_xor_sync(0xffffffffu, r, off));
            rmax[i] = r;
        }
    }
    float tval = 0.f;
    if (EPI == EPI_SUBROW_TAU) tval = tau[0];

    #pragma unroll
    for (int i = 0; i < TM; i++) {
        int r = row0 + tm * TM + i;
        if (r >= M) continue;
        float sub = 0.f;
        if (EPI == EPI_SUBROW || EPI == EPI_SUBROW_TAU) sub = aux[r];
        #pragma unroll
        for (int j = 0; j < TN; j++) {
            int cc = n0 + tn * TN + j;
            if (cc >= Nout) continue;
            float v = acc[i][j];
            if (EPI == EPI_POS) v += aux[(r % N_) * ldo + cc];
            else if (EPI == EPI_SUBROW) v -= sub;
            else if (EPI == EPI_SUBROW_TAU) v = fmaxf(v - sub, tval);
            else if (EPI == EPI_PNORM_RESID) v = fmaxf(O[(long)r * ldo + cc], v - rmax[i]);
            O[(long)r * ldo + cc] = v;
        }
    }
}

// ---------------- global pool over patches ----------------
__global__ void pool_kernel(const float* __restrict__ h, float* __restrict__ pool) {
    int idx = blockIdx.x * blockDim.x + threadIdx.x;
    if (idx >= B_ * D_) return;
    int d = idx % D_, b = idx / D_;
    float v = NEGBIG;
    for (int n = 0; n < N_; n++) v = fmaxf(v, h[((long)b * N_ + n) * D_ + d]);
    pool[idx] = v;
}

// ---------------- head: trop_mm(pooled, head_W) * logit_scale ----------------
__global__ void head_kernel(const float* __restrict__ pool, const float* __restrict__ W,
                            const float* __restrict__ scale, float* __restrict__ out) {
    int gw = (blockIdx.x * blockDim.x + threadIdx.x) >> 5;
    int lane = threadIdx.x & 31;
    if (gw >= B_ * C_) return;
    int c = gw % C_, b = gw / C_;
    float v = NEGBIG;
    #pragma unroll
    for (int i = 0; i < 4; i++) {
        int d = lane + i * 32;
        v = fmaxf(v, pool[b * D_ + d] + W[(long)c * D_ + d]);
    }
    #pragma unroll
    for (int off = 16; off; off >>= 1) v = fmaxf(v, __shfl_xor_sync(0xffffffffu, v, off));
    if (lane == 0) out[gw] = v * scale[0];
}

// ---------------- host ----------------
extern "C" void kernel_launch(void* const* d_in, const int* in_sizes, int n_in,
                              void* d_out, int out_size) {
    const float* x       = (const float*)d_in[0];
    const float* embed_W = (const float*)d_in[1];
    const float* pos     = (const float*)d_in[2];
    const float* qW[2]   = {(const float*)d_in[3],  (const float*)d_in[9]};
    const float* kW[2]   = {(const float*)d_in[4],  (const float*)d_in[10]};
    const float* vW[2]   = {(const float*)d_in[5],  (const float*)d_in[11]};
    const float* f1W[2]  = {(const float*)d_in[6],  (const float*)d_in[12]};
    const float* f2W[2]  = {(const float*)d_in[7],  (const float*)d_in[13]};
    const float* tau[2]  = {(const float*)d_in[8],  (const float*)d_in[14]};
    const float* headW   = (const float*)d_in[15];
    const float* lscale  = (const float*)d_in[16];
    float* out = (float*)d_out;

    float *p_patches, *p_h, *p_q, *p_k, *p_v, *p_S, *p_ff, *p_m, *p_pool;
    cudaGetSymbolAddress((void**)&p_patches, g_patches);
    cudaGetSymbolAddress((void**)&p_h, g_h);
    cudaGetSymbolAddress((void**)&p_q, g_q);
    cudaGetSymbolAddress((void**)&p_k, g_k);
    cudaGetSymbolAddress((void**)&p_v, g_v);
    cudaGetSymbolAddress((void**)&p_S, g_S);
    cudaGetSymbolAddress((void**)&p_ff, g_ff);
    cudaGetSymbolAddress((void**)&p_m, g_m);
    cudaGetSymbolAddress((void**)&p_pool, g_pool);

    const long tokD = (long)N_ * D_;

    // patchify
    patchify_kernel<<<(B_ * N_ * PD_ + 255) / 256, 256>>>(x);

    // embed: h = tropmm(patches, embed_W) + pos
    trop_gemm<32, 128, 16, 4, 4, EPI_POS><<<dim3(49, 1, 1), 256>>>(
        p_patches, PD_, 0, embed_W, PD_, 1, 0, p_h, D_, 0,
        M_, D_, PD_, pos, nullptr);

    for (int l = 0; l < 2; l++) {
        // m = rowmax(h)  (pnorm folded into qkv epilogue)
        rowmax_kernel<<<196, 256>>>(p_h, p_m, M_, D_);

        // q/k/v = tropmm(h, W) - m
        trop_gemm<32, 128, 16, 4, 4, EPI_SUBROW><<<dim3(49, 1, 1), 256>>>(
            p_h, D_, 0, qW[l], D_, 1, 0, p_q, D_, 0, M_, D_, D_, p_m, nullptr);
        trop_gemm<32, 128, 16, 4, 4, EPI_SUBROW><<<dim3(49, 1, 1), 256>>>(
            p_h, D_, 0, kW[l], D_, 1, 0, p_k, D_, 0, M_, D_, D_, p_m, nullptr);
        trop_gemm<32, 128, 16, 4, 4, EPI_SUBROW><<<dim3(49, 1, 1), 256>>>(
            p_h, D_, 0, vW[l], D_, 1, 0, p_v, D_, 0, M_, D_, D_, p_m, nullptr);

        // S[b,i,j] = max_d(q + k)   (batched: z = batch)
        trop_gemm<32, 128, 16, 4, 4, EPI_STORE><<<dim3(7, 2, 8), 256>>>(
            p_q, D_, tokD, p_k, D_, 1, tokD, p_S, N_, (long)N_ * N_,
            N_, N_, D_, nullptr, nullptr);

        // S -= rowmax_j
        snorm_kernel<<<196, 256>>>(p_S, B_ * N_, N_);

        // h = max(h, pnorm(max_j(S + v)))   (AV with fused pnorm + tropical residual)
        trop_gemm<16, 128, 16, 2, 4, EPI_PNORM_RESID><<<dim3(13, 1, 8), 256>>>(
            p_S, N_, (long)N_ * N_, p_v, 1, D_, tokD, p_h, D_, tokD,
            N_, D_, N_, nullptr, nullptr);

        // m = rowmax(h)
        rowmax_kernel<<<196, 256>>>(p_h, p_m, M_, D_);

        // ff = max(tropmm(h, f1W) - m, tau)
        trop_gemm<32, 128, 16, 4, 4, EPI_SUBROW_TAU><<<dim3(49, 2, 1), 256>>>(
            p_h, D_, 0, f1W[l], D_, 1, 0, p_ff, DFF_, 0, M_, DFF_, D_, p_m, tau[l]);

        // h = max(h, pnorm(tropmm(ff, f2W)))
        trop_gemm<32, 128, 16, 4, 4, EPI_PNORM_RESID><<<dim3(49, 1, 1), 256>>>(
            p_ff, DFF_, 0, f2W[l], DFF_, 1, 0, p_h, D_, 0,
            M_, D_, DFF_, nullptr, nullptr);
    }

    // tropical global pool + head
    pool_kernel<<<4, 256>>>(p_h, p_pool);
    head_kernel<<<1000, 256>>>(p_pool, headW, lscale, out);
}

// round 3
// speedup vs baseline: 1.4951x; 1.4951x over previous
#include <cuda_runtime.h>

// ---------------- problem dims ----------------
constexpr int B_   = 8;
constexpr int IMG_ = 224;
constexpr int G_   = 14;
constexpr int N_   = 196;   // G*G patches
constexpr int PD_  = 256;   // 16*16 patch dim
constexpr int D_   = 128;
constexpr int DFF_ = 256;
constexpr int C_   = 1000;
constexpr int M_   = B_ * N_;   // 1568 token rows

constexpr float NEGBIG = -1e30f;

// ---------------- scratch ----------------
__device__ float g_h[M_ * D_];
__device__ float g_qkv[3 * M_ * D_];
__device__ float g_S[B_ * N_ * N_];
__device__ float g_ff[M_ * DFF_];
__device__ float g_m[M_];
__device__ float g_pool[B_ * D_];

// epilogue modes
enum {
    EPI_STORE = 0,       // plain store
    EPI_POS_M = 1,       // v = acc + pos[(r%196)*ldo+cc]; also write rowmax -> mout
    EPI_SUBROW = 2,      // v = acc - aux[r]
    EPI_SUBROW_TAU = 3,  // v = max(acc - aux[r], tau[0])
    EPI_RESID_M = 4      // v = max(O_old, acc - rowmax(acc)); write rowmax(v) -> mout
};                       // (EPI_POS_M / EPI_RESID_M require BN >= Nout, full row per warp)

// ---------------- tropical GEMM ----------------
// out[r, n] = max_k ( A[r, k] + W[n*wN + k*wK] )  (+ epilogue)
// z (blockIdx.z): A += z*sA, O += z*sO, W = {W0,W1,W2}[z] if W1!=null else W0 + z*sW,
//                 aux/mout += z*sM.
template <int BM, int BN, int BK, int TM, int TN, int EPI, bool PATCH>
__global__ void __launch_bounds__((BM / TM) * (BN / TN))
trop_gemm(const float* __restrict__ A, int lda, long sA,
          const float* __restrict__ W0, const float* __restrict__ W1,
          const float* __restrict__ W2, int wN, int wK, long sW,
          float* __restrict__ O, int ldo, long sO,
          int M, int Nout, int K, long sM,
          const float* __restrict__ aux, float* __restrict__ mout,
          const float* __restrict__ tau) {
    constexpr int THREADS = (BM / TM) * (BN / TN);
    constexpr int APT = BM * BK / THREADS;
    constexpr int BPT = BN * BK / THREADS;

    __shared__ __align__(16) float As[2][BK][BM + 4];
    __shared__ __align__(16) float Bs[2][BK][BN + 4];

    const int z = blockIdx.z;
    A += (long)z * sA;
    O += (long)z * sO;
    const float* W;
    if (W1) W = (z == 0) ? W0 : (z == 1) ? W1 : W2;
    else    W = W0 + (long)z * sW;
    if (aux)  aux  += z * sM;
    if (mout) mout += z * sM;

    const int row0 = blockIdx.x * BM;
    const int n0 = blockIdx.y * BN;
    const int tid = threadIdx.x;
    const bool kcontig = (wK == 1);

    float apf[APT], bpf[BPT];
    const int nchunks = (K + BK - 1) / BK;

    auto loadA = [&](int c) {
        #pragma unroll
        for (int i = 0; i < APT; i++) {
            int e = tid + i * THREADS;
            int kk = e % BK, mm = e / BK;
            int k = c * BK + kk, r = row0 + mm;
            if (PATCH) {
                // A is raw image x: r -> (b, patch), k -> (pi, pj)
                int b = r / N_, n = r % N_;
                int gi = n / G_, gj = n % G_;
                int pi = k >> 4, pj = k & 15;
                apf[i] = A[((long)b * IMG_ + gi * 16 + pi) * IMG_ + gj * 16 + pj];
            } else {
                apf[i] = (r < M && k < K) ? A[(long)r * lda + k] : NEGBIG;
            }
        }
    };
    auto loadB = [&](int c) {
        if (kcontig) {
            #pragma unroll
            for (int i = 0; i < BPT; i++) {
                int e = tid + i * THREADS;
                int kk = e % BK, n = e / BK;
                int k = c * BK + kk, nn = n0 + n;
                bpf[i] = (nn < Nout && k < K) ? W[(long)nn * wN + k] : NEGBIG;
            }
        } else {
            #pragma unroll
            for (int i = 0; i < BPT; i++) {
                int e = tid + i * THREADS;
                int n = e % BN, kk = e / BN;
                int k = c * BK + kk, nn = n0 + n;
                bpf[i] = (nn < Nout && k < K) ? W[(long)k * wK + nn] : NEGBIG;
            }
        }
    };
    auto storeAB = [&](int s) {
        #pragma unroll
        for (int i = 0; i < APT; i++) {
            int e = tid + i * THREADS;
            As[s][e % BK][e / BK] = apf[i];
        }
        if (kcontig) {
            #pragma unroll
            for (int i = 0; i < BPT; i++) {
                int e = tid + i * THREADS;
                Bs[s][e % BK][e / BK] = bpf[i];
            }
        } else {
            #pragma unroll
            for (int i = 0; i < BPT; i++) {
                int e = tid + i * THREADS;
                Bs[s][e / BN][e % BN] = bpf[i];
            }
        }
    };

    float acc[TM][TN];
    #pragma unroll
    for (int i = 0; i < TM; i++)
        #pragma unroll
        for (int j = 0; j < TN; j++) acc[i][j] = NEGBIG;

    const int tn = tid & 31;    // BN/TN == 32 lanes cover the N tile
    const int tm = tid >> 5;

    loadA(0);
    loadB(0);
    storeAB(0);
    __syncthreads();

    for (int c = 0; c < nchunks; c++) {
        const int s = c & 1;
        const bool more = (c + 1 < nchunks);
        if (more) { loadA(c + 1); loadB(c + 1); }
        #pragma unroll
        for (int kk = 0; kk < BK; kk++) {
            float a[TM], b[TN];
            if (TM == 4) *reinterpret_cast<float4*>(a) =
                *reinterpret_cast<const float4*>(&As[s][kk][tm * TM]);
            else if (TM == 2) *reinterpret_cast<float2*>(a) =
                *reinterpret_cast<const float2*>(&As[s][kk][tm * TM]);
            else
                #pragma unroll
                for (int i = 0; i < TM; i++) a[i] = As[s][kk][tm * TM + i];
            #pragma unroll
            for (int j4 = 0; j4 < TN; j4 += 4)
                *reinterpret_cast<float4*>(&b[j4]) =
                    *reinterpret_cast<const float4*>(&Bs[s][kk][tn * TN + j4]);
            #pragma unroll
            for (int i = 0; i < TM; i++)
                #pragma unroll
                for (int j = 0; j < TN; j++)
                    acc[i][j] = fmaxf(acc[i][j], a[i] + b[j]);
        }
        if (more) {
            storeAB(s ^ 1);
            __syncthreads();
        }
    }

    // ---- epilogue ----
    float tval = 0.f;
    if (EPI == EPI_SUBROW_TAU) tval = tau[0];

    #pragma unroll
    for (int i = 0; i < TM; i++) {
        int r = row0 + tm * TM + i;
        if (r >= M) continue;
        float sub = 0.f;
        if (EPI == EPI_SUBROW || EPI == EPI_SUBROW_TAU) sub = aux[r];

        float v[TN];
        if (EPI == EPI_RESID_M) {
            float rmax = acc[i][0];
            #pragma unroll
            for (int j = 1; j < TN; j++) rmax = fmaxf(rmax, acc[i][j]);
            #pragma unroll
            for (int off = 16; off; off >>= 1)
                rmax = fmaxf(rmax, __shfl_xor_sync(0xffffffffu, rmax, off));
            #pragma unroll
            for (int j = 0; j < TN; j++) {
                int cc = n0 + tn * TN + j;
                v[j] = fmaxf(O[(long)r * ldo + cc], acc[i][j] - rmax);
            }
        } else if (EPI == EPI_POS_M) {
            #pragma unroll
            for (int j = 0; j < TN; j++) {
                int cc = n0 + tn * TN + j;
                v[j] = acc[i][j] + aux[(r % N_) * ldo + cc];
            }
        } else {
            #pragma unroll
            for (int j = 0; j < TN; j++) {
                float t = acc[i][j];
                if (EPI == EPI_SUBROW) t -= sub;
                else if (EPI == EPI_SUBROW_TAU) t = fmaxf(t - sub, tval);
                v[j] = t;
            }
        }

        #pragma unroll
        for (int j = 0; j < TN; j++) {
            int cc = n0 + tn * TN + j;
            if (cc < Nout) O[(long)r * ldo + cc] = v[j];
        }

        if (EPI == EPI_RESID_M || EPI == EPI_POS_M) {
            float nm = v[0];
            #pragma unroll
            for (int j = 1; j < TN; j++) nm = fmaxf(nm, v[j]);
            #pragma unroll
            for (int off = 16; off; off >>= 1)
                nm = fmaxf(nm, __shfl_xor_sync(0xffffffffu, nm, off));
            if (tn == 0) mout[r] = nm;
        }
    }
}

// ---------------- tropical global pool over patches ----------------
__global__ void pool_kernel(const float* __restrict__ h, float* __restrict__ pool) {
    int idx = blockIdx.x * blockDim.x + threadIdx.x;
    if (idx >= B_ * D_) return;
    int d = idx % D_, b = idx / D_;
    float v = NEGBIG;
    for (int n = 0; n < N_; n++) v = fmaxf(v, h[((long)b * N_ + n) * D_ + d]);
    pool[idx] = v;
}

// ---------------- head ----------------
__global__ void head_kernel(const float* __restrict__ pool, const float* __restrict__ W,
                            const float* __restrict__ scale, float* __restrict__ out) {
    int gw = (blockIdx.x * blockDim.x + threadIdx.x) >> 5;
    int lane = threadIdx.x & 31;
    if (gw >= B_ * C_) return;
    int c = gw % C_, b = gw / C_;
    float v = NEGBIG;
    #pragma unroll
    for (int i = 0; i < 4; i++) {
        int d = lane + i * 32;
        v = fmaxf(v, pool[b * D_ + d] + W[(long)c * D_ + d]);
    }
    #pragma unroll
    for (int off = 16; off; off >>= 1) v = fmaxf(v, __shfl_xor_sync(0xffffffffu, v, off));
    if (lane == 0) out[gw] = v * scale[0];
}

// ---------------- host ----------------
extern "C" void kernel_launch(void* const* d_in, const int* in_sizes, int n_in,
                              void* d_out, int out_size) {
    const float* x       = (const float*)d_in[0];
    const float* embed_W = (const float*)d_in[1];
    const float* pos     = (const float*)d_in[2];
    const float* qW[2]   = {(const float*)d_in[3],  (const float*)d_in[9]};
    const float* kW[2]   = {(const float*)d_in[4],  (const float*)d_in[10]};
    const float* vW[2]   = {(const float*)d_in[5],  (const float*)d_in[11]};
    const float* f1W[2]  = {(const float*)d_in[6],  (const float*)d_in[12]};
    const float* f2W[2]  = {(const float*)d_in[7],  (const float*)d_in[13]};
    const float* tau[2]  = {(const float*)d_in[8],  (const float*)d_in[14]};
    const float* headW   = (const float*)d_in[15];
    const float* lscale  = (const float*)d_in[16];
    float* out = (float*)d_out;

    float *p_h, *p_qkv, *p_S, *p_ff, *p_m, *p_pool;
    cudaGetSymbolAddress((void**)&p_h, g_h);
    cudaGetSymbolAddress((void**)&p_qkv, g_qkv);
    cudaGetSymbolAddress((void**)&p_S, g_S);
    cudaGetSymbolAddress((void**)&p_ff, g_ff);
    cudaGetSymbolAddress((void**)&p_m, g_m);
    cudaGetSymbolAddress((void**)&p_pool, g_pool);

    const long tokD = (long)N_ * D_;
    const long qkvS = (long)M_ * D_;

    // embed (patchify fused into A-load): h = tropmm(patches, embed_W) + pos; m = rowmax(h)
    trop_gemm<16, 128, 16, 2, 4, EPI_POS_M, true><<<dim3(98, 1, 1), 256>>>(
        x, 0, 0, embed_W, nullptr, nullptr, PD_, 1, 0,
        p_h, D_, 0, M_, D_, PD_, 0, pos, p_m, nullptr);

    for (int l = 0; l < 2; l++) {
        // q/k/v = tropmm(h, W) - m   (one launch, z selects weight; 147 blocks)
        trop_gemm<32, 128, 16, 4, 4, EPI_SUBROW, false><<<dim3(49, 1, 3), 256>>>(
            p_h, D_, 0, qW[l], kW[l], vW[l], D_, 1, 0,
            p_qkv, D_, qkvS, M_, D_, D_, 0, p_m, nullptr, nullptr);

        // S[b,i,j] = max_d(q_id + k_jd)   (no snorm needed: absorbed by later pnorm)
        trop_gemm<32, 128, 16, 4, 4, EPI_STORE, false><<<dim3(7, 2, 8), 256>>>(
            p_qkv, D_, tokD, p_qkv + qkvS, nullptr, nullptr, D_, 1, tokD,
            p_S, N_, (long)N_ * N_, N_, N_, D_, 0, nullptr, nullptr, nullptr);

        // h = max(h, pnorm(max_j(S + v)));  m = rowmax(h)
        trop_gemm<16, 128, 16, 2, 4, EPI_RESID_M, false><<<dim3(13, 1, 8), 256>>>(
            p_S, N_, (long)N_ * N_, p_qkv + 2 * qkvS, nullptr, nullptr, 1, D_, tokD,
            p_h, D_, tokD, N_, D_, N_, N_, nullptr, p_m, nullptr);

        // ff = max(tropmm(h, f1W) - m, tau)
        trop_gemm<32, 128, 16, 4, 4, EPI_SUBROW_TAU, false><<<dim3(49, 2, 1), 256>>>(
            p_h, D_, 0, f1W[l], nullptr, nullptr, D_, 1, 0,
            p_ff, DFF_, 0, M_, DFF_, D_, 0, p_m, nullptr, tau[l]);

        // h = max(h, pnorm(tropmm(ff, f2W)));  m = rowmax(h)
        trop_gemm<16, 128, 16, 2, 4, EPI_RESID_M, false><<<dim3(98, 1, 1), 256>>>(
            p_ff, DFF_, 0, f2W[l], nullptr, nullptr, DFF_, 1, 0,
            p_h, D_, 0, M_, D_, DFF_, 0, nullptr, p_m, nullptr);
    }

    pool_kernel<<<4, 256>>>(p_h, p_pool);
    head_kernel<<<1000, 256>>>(p_pool, headW, lscale, out);
}

// round 6
// speedup vs baseline: 1.4994x; 1.0029x over previous
#include <cuda_runtime.h>

// ---------------- problem dims ----------------
constexpr int B_   = 8;
constexpr int IMG_ = 224;
constexpr int G_   = 14;
constexpr int N_   = 196;   // G*G patches
constexpr int PD_  = 256;   // 16*16 patch dim
constexpr int D_   = 128;
constexpr int DFF_ = 256;
constexpr int C_   = 1000;
constexpr int M_   = B_ * N_;   // 1568 token rows

constexpr float NEGBIG = -1e30f;

// ---------------- scratch ----------------
__device__ float g_h[M_ * D_];
__device__ float g_qkv[3 * M_ * D_];
__device__ float g_S[B_ * N_ * N_];
__device__ float g_ff[M_ * DFF_];
__device__ float g_m[M_];
__device__ float g_pool[B_ * D_];

// epilogue modes
enum {
    EPI_STORE = 0,       // plain store
    EPI_POS_M = 1,       // v = acc + pos[(r%196)*ldo+cc]; also write rowmax -> mout
    EPI_SUBROW = 2,      // v = acc - aux[r]
    EPI_SUBROW_TAU = 3,  // v = max(acc - aux[r], tau[0])
    EPI_RESID_M = 4      // v = max(O_old, acc - rowmax(acc)); write rowmax(v) -> mout
};                       // (EPI_POS_M / EPI_RESID_M require BN == Nout == 32*TN)

// ---------------- tropical GEMM ----------------
// out[r, n] = max_k ( A[r, k] + W[n*wN + k*wK] )  (+ epilogue)
// z (blockIdx.z): A += z*sA, O += z*sO, W = {W0,W1,W2}[z] if W1!=null else W0 + z*sW,
//                 aux/mout += z*sM.
template <int BM, int BN, int BK, int TM, int TN, int EPI, bool PATCH>
__global__ void __launch_bounds__((BM / TM) * (BN / TN))
trop_gemm(const float* __restrict__ A, int lda, long sA,
          const float* __restrict__ W0, const float* __restrict__ W1,
          const float* __restrict__ W2, int wN, int wK, long sW,
          float* __restrict__ O, int ldo, long sO,
          int M, int Nout, int K, long sM,
          const float* __restrict__ aux, float* __restrict__ mout,
          const float* __restrict__ tau) {
    constexpr int THREADS = (BM / TM) * (BN / TN);   // (BN/TN) == 32 lanes per row
    static_assert(BN / TN == 32, "warp must span the N tile");
    constexpr int APT = BM * BK / THREADS;
    constexpr int BPT = BN * BK / THREADS;

    __shared__ __align__(16) float As[2][BK][BM + 4];
    __shared__ __align__(16) float Bs[2][BK][BN + 4];

    const int z = blockIdx.z;
    A += (long)z * sA;
    O += (long)z * sO;
    const float* W;
    if (W1) W = (z == 0) ? W0 : (z == 1) ? W1 : W2;
    else    W = W0 + (long)z * sW;
    if (aux)  aux  += z * sM;
    if (mout) mout += z * sM;

    const int row0 = blockIdx.x * BM;
    const int n0 = blockIdx.y * BN;
    const int tid = threadIdx.x;
    const bool kcontig = (wK == 1);

    float apf[APT], bpf[BPT];
    const int nchunks = (K + BK - 1) / BK;

    auto loadA = [&](int c) {
        #pragma unroll
        for (int i = 0; i < APT; i++) {
            int e = tid + i * THREADS;
            int kk = e % BK, mm = e / BK;
            int k = c * BK + kk, r = row0 + mm;
            if (PATCH) {
                // A is raw image x: r -> (b, patch), k -> (pi, pj)
                int b = r / N_, n = r % N_;
                int gi = n / G_, gj = n % G_;
                int pi = k >> 4, pj = k & 15;
                apf[i] = A[((long)b * IMG_ + gi * 16 + pi) * IMG_ + gj * 16 + pj];
            } else {
                apf[i] = (r < M && k < K) ? A[(long)r * lda + k] : NEGBIG;
            }
        }
    };
    auto loadB = [&](int c) {
        if (kcontig) {
            #pragma unroll
            for (int i = 0; i < BPT; i++) {
                int e = tid + i * THREADS;
                int kk = e % BK, n = e / BK;
                int k = c * BK + kk, nn = n0 + n;
                bpf[i] = (nn < Nout && k < K) ? W[(long)nn * wN + k] : NEGBIG;
            }
        } else {
            #pragma unroll
            for (int i = 0; i < BPT; i++) {
                int e = tid + i * THREADS;
                int n = e % BN, kk = e / BN;
                int k = c * BK + kk, nn = n0 + n;
                bpf[i] = (nn < Nout && k < K) ? W[(long)k * wK + nn] : NEGBIG;
            }
        }
    };
    auto storeAB = [&](int s) {
        #pragma unroll
        for (int i = 0; i < APT; i++) {
            int e = tid + i * THREADS;
            As[s][e % BK][e / BK] = apf[i];
        }
        if (kcontig) {
            #pragma unroll
            for (int i = 0; i < BPT; i++) {
                int e = tid + i * THREADS;
                Bs[s][e % BK][e / BK] = bpf[i];
            }
        } else {
            #pragma unroll
            for (int i = 0; i < BPT; i++) {
                int e = tid + i * THREADS;
                Bs[s][e / BN][e % BN] = bpf[i];
            }
        }
    };

    float acc[TM][TN];
    #pragma unroll
    for (int i = 0; i < TM; i++)
        #pragma unroll
        for (int j = 0; j < TN; j++) acc[i][j] = NEGBIG;

    const int tn = tid & 31;
    const int tm = tid >> 5;

    loadA(0);
    loadB(0);
    storeAB(0);
    __syncthreads();

    for (int c = 0; c < nchunks; c++) {
        const int s = c & 1;
        const bool more = (c + 1 < nchunks);
        if (more) { loadA(c + 1); loadB(c + 1); }
        #pragma unroll
        for (int kk = 0; kk < BK; kk++) {
            float a[TM], b[TN];
            if (TM == 4) *reinterpret_cast<float4*>(a) =
                *reinterpret_cast<const float4*>(&As[s][kk][tm * TM]);
            else if (TM == 2) *reinterpret_cast<float2*>(a) =
                *reinterpret_cast<const float2*>(&As[s][kk][tm * TM]);
            else
                #pragma unroll
                for (int i = 0; i < TM; i++) a[i] = As[s][kk][tm * TM + i];
            if (TN == 4) {
                *reinterpret_cast<float4*>(b) =
                    *reinterpret_cast<const float4*>(&Bs[s][kk][tn * TN]);
            } else {
                *reinterpret_cast<float2*>(b) =
                    *reinterpret_cast<const float2*>(&Bs[s][kk][tn * TN]);
            }
            #pragma unroll
            for (int i = 0; i < TM; i++)
                #pragma unroll
                for (int j = 0; j < TN; j++)
                    acc[i][j] = fmaxf(acc[i][j], a[i] + b[j]);
        }
        if (more) {
            storeAB(s ^ 1);
            __syncthreads();
        }
    }

    // ---- epilogue ----
    float tval = 0.f;
    if (EPI == EPI_SUBROW_TAU) tval = tau[0];

    #pragma unroll
    for (int i = 0; i < TM; i++) {
        int r = row0 + tm * TM + i;
        if (r >= M) continue;
        float sub = 0.f;
        if (EPI == EPI_SUBROW || EPI == EPI_SUBROW_TAU) sub = aux[r];

        float v[TN];
        if (EPI == EPI_RESID_M) {
            float rmax = acc[i][0];
            #pragma unroll
            for (int j = 1; j < TN; j++) rmax = fmaxf(rmax, acc[i][j]);
            #pragma unroll
            for (int off = 16; off; off >>= 1)
                rmax = fmaxf(rmax, __shfl_xor_sync(0xffffffffu, rmax, off));
            #pragma unroll
            for (int j = 0; j < TN; j++) {
                int cc = n0 + tn * TN + j;
                v[j] = fmaxf(O[(long)r * ldo + cc], acc[i][j] - rmax);
            }
        } else if (EPI == EPI_POS_M) {
            #pragma unroll
            for (int j = 0; j < TN; j++) {
                int cc = n0 + tn * TN + j;
                v[j] = acc[i][j] + aux[(r % N_) * ldo + cc];
            }
        } else {
            #pragma unroll
            for (int j = 0; j < TN; j++) {
                float t = acc[i][j];
                if (EPI == EPI_SUBROW) t -= sub;
                else if (EPI == EPI_SUBROW_TAU) t = fmaxf(t - sub, tval);
                v[j] = t;
            }
        }

        #pragma unroll
        for (int j = 0; j < TN; j++) {
            int cc = n0 + tn * TN + j;
            if (cc < Nout) O[(long)r * ldo + cc] = v[j];
        }

        if (EPI == EPI_RESID_M || EPI == EPI_POS_M) {
            float nm = v[0];
            #pragma unroll
            for (int j = 1; j < TN; j++) nm = fmaxf(nm, v[j]);
            #pragma unroll
            for (int off = 16; off; off >>= 1)
                nm = fmaxf(nm, __shfl_xor_sync(0xffffffffu, nm, off));
            if (tn == 0) mout[r] = nm;
        }
    }
}

// ---------------- tropical global pool over patches ----------------
__global__ void pool_kernel(const float* __restrict__ h, float* __restrict__ pool) {
    int idx = blockIdx.x * blockDim.x + threadIdx.x;
    if (idx >= B_ * D_) return;
    int d = idx % D_, b = idx / D_;
    float v = NEGBIG;
    for (int n = 0; n < N_; n++) v = fmaxf(v, h[((long)b * N_ + n) * D_ + d]);
    pool[idx] = v;
}

// ---------------- head ----------------
__global__ void head_kernel(const float* __restrict__ pool, const float* __restrict__ W,
                            const float* __restrict__ scale, float* __restrict__ out) {
    int gw = (blockIdx.x * blockDim.x + threadIdx.x) >> 5;
    int lane = threadIdx.x & 31;
    if (gw >= B_ * C_) return;
    int c = gw % C_, b = gw / C_;
    float v = NEGBIG;
    #pragma unroll
    for (int i = 0; i < 4; i++) {
        int d = lane + i * 32;
        v = fmaxf(v, pool[b * D_ + d] + W[(long)c * D_ + d]);
    }
    #pragma unroll
    for (int off = 16; off; off >>= 1) v = fmaxf(v, __shfl_xor_sync(0xffffffffu, v, off));
    if (lane == 0) out[gw] = v * scale[0];
}

// ---------------- host ----------------
extern "C" void kernel_launch(void* const* d_in, const int* in_sizes, int n_in,
                              void* d_out, int out_size) {
    const float* x       = (const float*)d_in[0];
    const float* embed_W = (const float*)d_in[1];
    const float* pos     = (const float*)d_in[2];
    const float* qW[2]   = {(const float*)d_in[3],  (const float*)d_in[9]};
    const float* kW[2]   = {(const float*)d_in[4],  (const float*)d_in[10]};
    const float* vW[2]   = {(const float*)d_in[5],  (const float*)d_in[11]};
    const float* f1W[2]  = {(const float*)d_in[6],  (const float*)d_in[12]};
    const float* f2W[2]  = {(const float*)d_in[7],  (const float*)d_in[13]};
    const float* tau[2]  = {(const float*)d_in[8],  (const float*)d_in[14]};
    const float* headW   = (const float*)d_in[15];
    const float* lscale  = (const float*)d_in[16];
    float* out = (float*)d_out;

    float *p_h, *p_qkv, *p_S, *p_ff, *p_m, *p_pool;
    cudaGetSymbolAddress((void**)&p_h, g_h);
    cudaGetSymbolAddress((void**)&p_qkv, g_qkv);
    cudaGetSymbolAddress((void**)&p_S, g_S);
    cudaGetSymbolAddress((void**)&p_ff, g_ff);
    cudaGetSymbolAddress((void**)&p_m, g_m);
    cudaGetSymbolAddress((void**)&p_pool, g_pool);

    const long tokD = (long)N_ * D_;
    const long qkvS = (long)M_ * D_;

    // embed (patchify fused): h = tropmm(patches, embed_W) + pos; m = rowmax(h)
    // grid 196 x 128 threads
    trop_gemm<8, 128, 16, 2, 4, EPI_POS_M, true><<<dim3(196, 1, 1), 128>>>(
        x, 0, 0, embed_W, nullptr, nullptr, PD_, 1, 0,
        p_h, D_, 0, M_, D_, PD_, 0, pos, p_m, nullptr);

    for (int l = 0; l < 2; l++) {
        // q/k/v = tropmm(h, W) - m   (z selects weight; 588 blocks)
        trop_gemm<8, 128, 16, 2, 4, EPI_SUBROW, false><<<dim3(196, 1, 3), 128>>>(
            p_h, D_, 0, qW[l], kW[l], vW[l], D_, 1, 0,
            p_qkv, D_, qkvS, M_, D_, D_, 0, p_m, nullptr, nullptr);

        // S[b,i,j] = max_d(q_id + k_jd)   (snorm absorbed by later pnorm) — 416 blocks
        trop_gemm<16, 64, 16, 4, 2, EPI_STORE, false><<<dim3(13, 4, 8), 128>>>(
            p_qkv, D_, tokD, p_qkv + qkvS, nullptr, nullptr, D_, 1, tokD,
            p_S, N_, (long)N_ * N_, N_, N_, D_, 0, nullptr, nullptr, nullptr);

        // h = max(h, pnorm(max_j(S + v)));  m = rowmax(h) — 200 blocks
        trop_gemm<8, 128, 16, 2, 4, EPI_RESID_M, false><<<dim3(25, 1, 8), 128>>>(
            p_S, N_, (long)N_ * N_, p_qkv + 2 * qkvS, nullptr, nullptr, 1, D_, tokD,
            p_h, D_, tokD, N_, D_, N_, N_, nullptr, p_m, nullptr);

        // ff = max(tropmm(h, f1W) - m, tau) — 392 blocks
        trop_gemm<8, 128, 16, 2, 4, EPI_SUBROW_TAU, false><<<dim3(196, 2, 1), 128>>>(
            p_h, D_, 0, f1W[l], nullptr, nullptr, D_, 1, 0,
            p_ff, DFF_, 0, M_, DFF_, D_, 0, p_m, nullptr, tau[l]);

        // h = max(h, pnorm(tropmm(ff, f2W)));  m = rowmax(h) — 196 blocks
        trop_gemm<8, 128, 16, 2, 4, EPI_RESID_M, false><<<dim3(196, 1, 1), 128>>>(
            p_ff, DFF_, 0, f2W[l], nullptr, nullptr, DFF_, 1, 0,
            p_h, D_, 0, M_, D_, DFF_, 0, nullptr, p_m, nullptr);
    }

    pool_kernel<<<4, 256>>>(p_h, p_pool);
    head_kernel<<<1000, 256>>>(p_pool, headW, lscale, out);
}

// round 7
// speedup vs baseline: 1.6843x; 1.1233x over previous
#include <cuda_runtime.h>

// ---------------- problem dims ----------------
constexpr int B_   = 8;
constexpr int IMG_ = 224;
constexpr int G_   = 14;
constexpr int N_   = 196;   // G*G patches
constexpr int PD_  = 256;   // 16*16 patch dim
constexpr int D_   = 128;
constexpr int DFF_ = 256;
constexpr int C_   = 1000;
constexpr int M_   = B_ * N_;   // 1568 token rows

constexpr float NEGBIG = -1e30f;

// ---------------- scratch ----------------
__device__ float g_h[M_ * D_];
__device__ float g_qkv[3 * M_ * D_];
__device__ float g_S[B_ * N_ * N_];
__device__ float g_ff[M_ * DFF_];
__device__ float g_m[M_];
__device__ float g_pool[B_ * D_];

// epilogue modes
enum {
    EPI_STORE = 0,       // plain store
    EPI_POS_M = 1,       // v = acc + pos[(r%196)*ldo+cc]; also write rowmax -> mout
    EPI_SUBROW = 2,      // v = acc - aux[r]
    EPI_SUBROW_TAU = 3,  // v = max(acc - aux[r], tau[0])
    EPI_RESID_M = 4      // v = max(O_old, acc - rowmax(acc)); write rowmax(v) -> mout
};                       // (EPI_POS_M / EPI_RESID_M require BN == Nout == 32*TN)

// ---------------- tropical GEMM ----------------
// out[r, n] = max_k ( A[r, k] + W[n*wN + k*wK] )  (+ epilogue)
// z (blockIdx.z): A += z*sA, O += z*sO, W = {W0,W1,W2}[z] if W1!=null else W0 + z*sW,
//                 aux/mout += z*sM.
template <int BM, int BN, int BK, int TM, int TN, int EPI, bool PATCH, bool KCONTIG>
__global__ void __launch_bounds__((BM / TM) * (BN / TN))
trop_gemm(const float* __restrict__ A, int lda, long sA,
          const float* __restrict__ W0, const float* __restrict__ W1,
          const float* __restrict__ W2, int wN, int wK, long sW,
          float* __restrict__ O, int ldo, long sO,
          int M, int Nout, int K, long sM,
          const float* __restrict__ aux, float* __restrict__ mout,
          const float* __restrict__ tau) {
    constexpr int THREADS = (BM / TM) * (BN / TN);   // (BN/TN) == 32 lanes per row
    static_assert(BN / TN == 32, "warp must span the N tile");
    static_assert(BK % 4 == 0, "");
    constexpr int VA = BM * BK / 4;           // float4 loads for A tile
    constexpr int VB = BN * BK / 4;           // float4 loads for B tile
    constexpr int ITA = (VA + THREADS - 1) / THREADS;
    constexpr int ITB = (VB + THREADS - 1) / THREADS;

    __shared__ __align__(16) float As[2][BK][BM + 4];
    __shared__ __align__(16) float Bs[2][BK][BN + 4];

    const int z = blockIdx.z;
    A += (long)z * sA;
    O += (long)z * sO;
    const float* W;
    if (W1) W = (z == 0) ? W0 : (z == 1) ? W1 : W2;
    else    W = W0 + (long)z * sW;
    if (aux)  aux  += z * sM;
    if (mout) mout += z * sM;

    const int row0 = blockIdx.x * BM;
    const int n0 = blockIdx.y * BN;
    const int tid = threadIdx.x;

    float4 apf[ITA], bpf[ITB];
    const int nchunks = (K + BK - 1) / BK;

    auto loadA = [&](int c) {
        #pragma unroll
        for (int i = 0; i < ITA; i++) {
            int t = tid + i * THREADS;
            if ((VA % THREADS) && t >= VA) break;
            int flat = t * 4;
            int kk = flat % BK, mm = flat / BK;
            int k = c * BK + kk, r = row0 + mm;
            float4 v;
            if (PATCH) {
                // A is raw image x: r -> (b, patch), k -> (pi, pj); pj contiguous
                int b = r / N_, n = r % N_;
                int gi = n / G_, gj = n % G_;
                int pi = k >> 4, pj = k & 15;
                v = *reinterpret_cast<const float4*>(
                    &A[((long)b * IMG_ + gi * 16 + pi) * IMG_ + gj * 16 + pj]);
            } else if (r < M) {
                if (k + 3 < K) {
                    v = *reinterpret_cast<const float4*>(&A[(long)r * lda + k]);
                } else {
                    v.x = (k + 0 < K) ? A[(long)r * lda + k + 0] : NEGBIG;
                    v.y = (k + 1 < K) ? A[(long)r * lda + k + 1] : NEGBIG;
                    v.z = (k + 2 < K) ? A[(long)r * lda + k + 2] : NEGBIG;
                    v.w = (k + 3 < K) ? A[(long)r * lda + k + 3] : NEGBIG;
                }
            } else {
                v = make_float4(NEGBIG, NEGBIG, NEGBIG, NEGBIG);
            }
            apf[i] = v;
        }
    };
    auto loadB = [&](int c) {
        #pragma unroll
        for (int i = 0; i < ITB; i++) {
            int t = tid + i * THREADS;
            if ((VB % THREADS) && t >= VB) break;
            int flat = t * 4;
            float4 v;
            if (KCONTIG) {
                // K is the contiguous dim of W (all weight matrices): vec along k.
                // All KCONTIG call sites have K % BK == 0, so no k guard needed.
                int kk = flat % BK;
                int nn = n0 + flat / BK;
                int k = c * BK + kk;
                if (nn < Nout) {
                    v = *reinterpret_cast<const float4*>(&W[(long)nn * wN + k]);
                } else {
                    v = make_float4(NEGBIG, NEGBIG, NEGBIG, NEGBIG);
                }
            } else {
                // N is the contiguous dim (v operand of AV): vec along n.
                int n = flat % BN;
                int kk = flat / BN;
                int k = c * BK + kk;
                if (k < K) {
                    v = *reinterpret_cast<const float4*>(&W[(long)k * wK + n0 + n]);
                } else {
                    v = make_float4(NEGBIG, NEGBIG, NEGBIG, NEGBIG);
                }
            }
            bpf[i] = v;
        }
    };
    auto storeAB = [&](int s) {
        #pragma unroll
        for (int i = 0; i < ITA; i++) {
            int t = tid + i * THREADS;
            if ((VA % THREADS) && t >= VA) break;
            int flat = t * 4;
            int kk = flat % BK, mm = flat / BK;
            As[s][kk + 0][mm] = apf[i].x;
            As[s][kk + 1][mm] = apf[i].y;
            As[s][kk + 2][mm] = apf[i].z;
            As[s][kk + 3][mm] = apf[i].w;
        }
        #pragma unroll
        for (int i = 0; i < ITB; i++) {
            int t = tid + i * THREADS;
            if ((VB % THREADS) && t >= VB) break;
            int flat = t * 4;
            if (KCONTIG) {
                int kk = flat % BK, n = flat / BK;
                Bs[s][kk + 0][n] = bpf[i].x;
                Bs[s][kk + 1][n] = bpf[i].y;
                Bs[s][kk + 2][n] = bpf[i].z;
                Bs[s][kk + 3][n] = bpf[i].w;
            } else {
                int n = flat % BN, kk = flat / BN;
                *reinterpret_cast<float4*>(&Bs[s][kk][n]) = bpf[i];
            }
        }
    };

    float acc[TM][TN];
    #pragma unroll
    for (int i = 0; i < TM; i++)
        #pragma unroll
        for (int j = 0; j < TN; j++) acc[i][j] = NEGBIG;

    const int tn = tid & 31;
    const int tm = tid >> 5;

    loadA(0);
    loadB(0);
    storeAB(0);
    __syncthreads();

    for (int c = 0; c < nchunks; c++) {
        const int s = c & 1;
        const bool more = (c + 1 < nchunks);
        if (more) { loadA(c + 1); loadB(c + 1); }
        #pragma unroll
        for (int kk = 0; kk < BK; kk++) {
            float a[TM], b[TN];
            if (TM == 4) *reinterpret_cast<float4*>(a) =
                *reinterpret_cast<const float4*>(&As[s][kk][tm * TM]);
            else if (TM == 2) *reinterpret_cast<float2*>(a) =
                *reinterpret_cast<const float2*>(&As[s][kk][tm * TM]);
            else
                #pragma unroll
                for (int i = 0; i < TM; i++) a[i] = As[s][kk][tm * TM + i];
            if (TN == 4) {
                *reinterpret_cast<float4*>(b) =
                    *reinterpret_cast<const float4*>(&Bs[s][kk][tn * TN]);
            } else {
                *reinterpret_cast<float2*>(b) =
                    *reinterpret_cast<const float2*>(&Bs[s][kk][tn * TN]);
            }
            #pragma unroll
            for (int i = 0; i < TM; i++)
                #pragma unroll
                for (int j = 0; j < TN; j++)
                    acc[i][j] = fmaxf(acc[i][j], a[i] + b[j]);
        }
        if (more) {
            storeAB(s ^ 1);
            __syncthreads();
        }
    }

    // ---- epilogue ----
    float tval = 0.f;
    if (EPI == EPI_SUBROW_TAU) tval = tau[0];

    #pragma unroll
    for (int i = 0; i < TM; i++) {
        int r = row0 + tm * TM + i;
        if (r >= M) continue;
        float sub = 0.f;
        if (EPI == EPI_SUBROW || EPI == EPI_SUBROW_TAU) sub = aux[r];

        float v[TN];
        if (EPI == EPI_RESID_M) {
            float rmax = acc[i][0];
            #pragma unroll
            for (int j = 1; j < TN; j++) rmax = fmaxf(rmax, acc[i][j]);
            #pragma unroll
            for (int off = 16; off; off >>= 1)
                rmax = fmaxf(rmax, __shfl_xor_sync(0xffffffffu, rmax, off));
            #pragma unroll
            for (int j = 0; j < TN; j++) {
                int cc = n0 + tn * TN + j;
                v[j] = fmaxf(O[(long)r * ldo + cc], acc[i][j] - rmax);
            }
        } else if (EPI == EPI_POS_M) {
            #pragma unroll
            for (int j = 0; j < TN; j++) {
                int cc = n0 + tn * TN + j;
                v[j] = acc[i][j] + aux[(r % N_) * ldo + cc];
            }
        } else {
            #pragma unroll
            for (int j = 0; j < TN; j++) {
                float t = acc[i][j];
                if (EPI == EPI_SUBROW) t -= sub;
                else if (EPI == EPI_SUBROW_TAU) t = fmaxf(t - sub, tval);
                v[j] = t;
            }
        }

        #pragma unroll
        for (int j = 0; j < TN; j++) {
            int cc = n0 + tn * TN + j;
            if (cc < Nout) O[(long)r * ldo + cc] = v[j];
        }

        if (EPI == EPI_RESID_M || EPI == EPI_POS_M) {
            float nm = v[0];
            #pragma unroll
            for (int j = 1; j < TN; j++) nm = fmaxf(nm, v[j]);
            #pragma unroll
            for (int off = 16; off; off >>= 1)
                nm = fmaxf(nm, __shfl_xor_sync(0xffffffffu, nm, off));
            if (tn == 0) mout[r] = nm;
        }
    }
}

// ---------------- tropical global pool over patches ----------------
__global__ void pool_kernel(const float* __restrict__ h, float* __restrict__ pool) {
    int idx = blockIdx.x * blockDim.x + threadIdx.x;
    if (idx >= B_ * D_) return;
    int d = idx % D_, b = idx / D_;
    float v = NEGBIG;
    for (int n = 0; n < N_; n++) v = fmaxf(v, h[((long)b * N_ + n) * D_ + d]);
    pool[idx] = v;
}

// ---------------- head ----------------
__global__ void head_kernel(const float* __restrict__ pool, const float* __restrict__ W,
                            const float* __restrict__ scale, float* __restrict__ out) {
    int gw = (blockIdx.x * blockDim.x + threadIdx.x) >> 5;
    int lane = threadIdx.x & 31;
    if (gw >= B_ * C_) return;
    int c = gw % C_, b = gw / C_;
    float v = NEGBIG;
    #pragma unroll
    for (int i = 0; i < 4; i++) {
        int d = lane + i * 32;
        v = fmaxf(v, pool[b * D_ + d] + W[(long)c * D_ + d]);
    }
    #pragma unroll
    for (int off = 16; off; off >>= 1) v = fmaxf(v, __shfl_xor_sync(0xffffffffu, v, off));
    if (lane == 0) out[gw] = v * scale[0];
}

// ---------------- host ----------------
extern "C" void kernel_launch(void* const* d_in, const int* in_sizes, int n_in,
                              void* d_out, int out_size) {
    const float* x       = (const float*)d_in[0];
    const float* embed_W = (const float*)d_in[1];
    const float* pos     = (const float*)d_in[2];
    const float* qW[2]   = {(const float*)d_in[3],  (const float*)d_in[9]};
    const float* kW[2]   = {(const float*)d_in[4],  (const float*)d_in[10]};
    const float* vW[2]   = {(const float*)d_in[5],  (const float*)d_in[11]};
    const float* f1W[2]  = {(const float*)d_in[6],  (const float*)d_in[12]};
    const float* f2W[2]  = {(const float*)d_in[7],  (const float*)d_in[13]};
    const float* tau[2]  = {(const float*)d_in[8],  (const float*)d_in[14]};
    const float* headW   = (const float*)d_in[15];
    const float* lscale  = (const float*)d_in[16];
    float* out = (float*)d_out;

    float *p_h, *p_qkv, *p_S, *p_ff, *p_m, *p_pool;
    cudaGetSymbolAddress((void**)&p_h, g_h);
    cudaGetSymbolAddress((void**)&p_qkv, g_qkv);
    cudaGetSymbolAddress((void**)&p_S, g_S);
    cudaGetSymbolAddress((void**)&p_ff, g_ff);
    cudaGetSymbolAddress((void**)&p_m, g_m);
    cudaGetSymbolAddress((void**)&p_pool, g_pool);

    const long tokD = (long)N_ * D_;
    const long qkvS = (long)M_ * D_;

    // embed (patchify fused): h = tropmm(patches, embed_W) + pos; m = rowmax(h)
    trop_gemm<8, 128, 16, 2, 4, EPI_POS_M, true, true><<<dim3(196, 1, 1), 128>>>(
        x, 0, 0, embed_W, nullptr, nullptr, PD_, 1, 0,
        p_h, D_, 0, M_, D_, PD_, 0, pos, p_m, nullptr);

    for (int l = 0; l < 2; l++) {
        // q/k/v = tropmm(h, W) - m  (294 blocks x 8 warps)
        trop_gemm<16, 128, 16, 2, 4, EPI_SUBROW, false, true><<<dim3(98, 1, 3), 256>>>(
            p_h, D_, 0, qW[l], kW[l], vW[l], D_, 1, 0,
            p_qkv, D_, qkvS, M_, D_, D_, 0, p_m, nullptr, nullptr);

        // S[b,i,j] = max_d(q_id + k_jd)  (snorm absorbed by later pnorm) — 416 blocks
        trop_gemm<16, 64, 16, 4, 2, EPI_STORE, false, true><<<dim3(13, 4, 8), 128>>>(
            p_qkv, D_, tokD, p_qkv + qkvS, nullptr, nullptr, D_, 1, tokD,
            p_S, N_, (long)N_ * N_, N_, N_, D_, 0, nullptr, nullptr, nullptr);

        // h = max(h, pnorm(max_j(S + v)));  m = rowmax(h) — 200 blocks
        trop_gemm<8, 128, 16, 2, 4, EPI_RESID_M, false, false><<<dim3(25, 1, 8), 128>>>(
            p_S, N_, (long)N_ * N_, p_qkv + 2 * qkvS, nullptr, nullptr, 1, D_, tokD,
            p_h, D_, tokD, N_, D_, N_, N_, nullptr, p_m, nullptr);

        // ff = max(tropmm(h, f1W) - m, tau) — 392 blocks
        trop_gemm<8, 128, 16, 2, 4, EPI_SUBROW_TAU, false, true><<<dim3(196, 2, 1), 128>>>(
            p_h, D_, 0, f1W[l], nullptr, nullptr, D_, 1, 0,
            p_ff, DFF_, 0, M_, DFF_, D_, 0, p_m, nullptr, tau[l]);

        // h = max(h, pnorm(tropmm(ff, f2W)));  m = rowmax(h) — 196 blocks
        trop_gemm<8, 128, 16, 2, 4, EPI_RESID_M, false, true><<<dim3(196, 1, 1), 128>>>(
            p_ff, DFF_, 0, f2W[l], nullptr, nullptr, DFF_, 1, 0,
            p_h, D_, 0, M_, D_, DFF_, 0, nullptr, p_m, nullptr);
    }

    pool_kernel<<<8, 128>>>(p_h, p_pool);
    head_kernel<<<1000, 256>>>(p_pool, headW, lscale, out);
}